// round 9
// baseline (speedup 1.0000x reference)
#include <cuda_runtime.h>
#include <math_constants.h>
#include <cstdint>

// ChamferDistanceLoss, B=8, N=4096, D=3 — fused both directions.
// d(i,j) = rn_i + cn_j - 2 p1_i.p2_j computed ONCE per pair.
// Block = (batch, 128-row tile, 1024-col tile): 1024 blocks, all resident in
// ONE wave (launch_bounds(128,8) -> <=64 regs -> 8 blocks/SM, 148*8=1184>=1024).
// Warp owns a 256-col slice and ALL 128 rows (4/lane). XOR rotation: lane l
// at step s evaluates column l^s; one shfl_xor routes the column value to its
// owner lane; owner writes the final col-min straight to gmem.

#define NPTS 4096
#define BATCH 8
#define RPB 128
#define CPB 1024
#define RT 32
#define CT 4
#define MAIN_BLOCKS (BATCH * RT * CT)       // 1024
#define THREADS 128
#define NWARPS 4
#define WCOLS (CPB / NWARPS)                // 256
#define RED_THREADS 256
#define RED_BLOCKS (BATCH * NPTS / RED_THREADS)  // 128

__device__ float g_rowpart[MAIN_BLOCKS * NWARPS * RPB];  // 2 MB
__device__ float g_colpart[MAIN_BLOCKS * CPB];           // 4 MB
__device__ float g_sum[RED_BLOCKS];
__device__ unsigned int g_ticket;                        // zero-init; reset each call

// ---------------------------------------------------------------------------
__global__ void __launch_bounds__(THREADS, 8)
chamfer_main(const float* __restrict__ p1, const float* __restrict__ p2) {
    __shared__ float4 sc[CPB];               // (-2x,-2y,-2z,|c|^2)  16 KB

    int bx = blockIdx.x;
    int b  = bx >> 7;                        // batch
    int rt = (bx >> 2) & 31;                 // row tile
    int ct = bx & 3;                         // col tile
    const float* __restrict__ rows = p1 + (b * NPTS + rt * RPB) * 3;
    const float* __restrict__ cols = p2 + (b * NPTS + ct * CPB) * 3;

    int t = threadIdx.x, w = t >> 5, lane = t & 31;

    // Stage 1024 candidates: 8 per thread via 2 groups of 3x LDG.128.
    #pragma unroll
    for (int g = 0; g < CPB / (4 * THREADS); ++g) {
        int ci = t + g * THREADS;
        const float4* s4 = (const float4*)cols + 3 * ci;
        float4 v0 = s4[0], v1 = s4[1], v2 = s4[2];
        float cx[4] = { v0.x, v0.w, v1.z, v2.y };
        float cy[4] = { v0.y, v1.x, v1.w, v2.z };
        float cz[4] = { v0.z, v1.y, v2.x, v2.w };
        #pragma unroll
        for (int k = 0; k < 4; ++k) {
            float x = cx[k], y = cy[k], z = cz[k];
            float n = fmaf(x, x, fmaf(y, y, z * z));
            sc[4 * ci + k] = make_float4(-2.0f * x, -2.0f * y, -2.0f * z, n);
        }
    }

    // 4 rows per lane (whole 128-row tile per warp).
    float rx[4], ry[4], rz[4], rn[4], rm[4];
    #pragma unroll
    for (int k = 0; k < 4; ++k) {
        int r = k * 32 + lane;
        rx[k] = rows[3 * r + 0];
        ry[k] = rows[3 * r + 1];
        rz[k] = rows[3 * r + 2];
        rn[k] = fmaf(rx[k], rx[k], fmaf(ry[k], ry[k], rz[k] * rz[k]));
        rm[k] = CUDART_INF_F;
    }
    __syncthreads();

    const char* sbase = (const char*)sc;
    #pragma unroll
    for (int cc = 0; cc < WCOLS / 32; ++cc) {            // 8 groups of 32 cols
        uint32_t off0 = (uint32_t)(w * WCOLS + cc * 32 + lane) * 16u;
        float cm = CUDART_INF_F;
        #pragma unroll 8
        for (int s = 0; s < 32; ++s) {
            float4 c = *(const float4*)(sbase + (off0 ^ ((uint32_t)s << 4)));
            float w0 = fmaf(c.x, rx[0], fmaf(c.y, ry[0], fmaf(c.z, rz[0], c.w + rn[0])));
            float w1 = fmaf(c.x, rx[1], fmaf(c.y, ry[1], fmaf(c.z, rz[1], c.w + rn[1])));
            float w2 = fmaf(c.x, rx[2], fmaf(c.y, ry[2], fmaf(c.z, rz[2], c.w + rn[2])));
            float w3 = fmaf(c.x, rx[3], fmaf(c.y, ry[3], fmaf(c.z, rz[3], c.w + rn[3])));
            rm[0] = fminf(rm[0], w0);
            rm[1] = fminf(rm[1], w1);
            rm[2] = fminf(rm[2], w2);
            rm[3] = fminf(rm[3], w3);
            float cv = fminf(fminf(w0, w1), fminf(w2, w3));
            cm = fminf(cm, __shfl_xor_sync(0xffffffffu, cv, s));
        }
        // This warp reduced column (base + lane) over all 128 rows: final partial.
        g_colpart[bx * CPB + w * WCOLS + cc * 32 + lane] = cm;
    }

    // Row partials: full-d min over this warp's 256 cols (rn already folded in).
    #pragma unroll
    for (int k = 0; k < 4; ++k)
        g_rowpart[(bx * NWARPS + w) * RPB + k * 32 + lane] = rm[k];
}

// ---------------------------------------------------------------------------
// Reduce: thread i owns global row i and global col i (both 0..32767):
// row-min over 16 partials (4 ct x 4 warps), col-min over 32 partials (rt).
// Last block (threadfence ticket) sums the 128 block partials -> loss.
// ---------------------------------------------------------------------------
__global__ void chamfer_reduce(float* __restrict__ out) {
    __shared__ float wsum[RED_THREADS / 32];
    __shared__ bool s_last;
    int i = blockIdx.x * RED_THREADS + threadIdx.x;      // 0..32767
    int b = i >> 12;
    int r = i & (NPTS - 1);

    // Row side: (b, rt=r>>7, rr=r&127), min over ct, w.
    int rt = r >> 7, rr = r & 127;
    float rmin = CUDART_INF_F;
    #pragma unroll
    for (int c = 0; c < CT; ++c)
        #pragma unroll
        for (int ww = 0; ww < NWARPS; ++ww)
            rmin = fminf(rmin,
                g_rowpart[(((b * RT + rt) * CT + c) * NWARPS + ww) * RPB + rr]);

    // Col side: (b, ctile=r>>10, cc=r&1023), min over rt.
    int ctile = r >> 10, ccx = r & (CPB - 1);
    float cmin = CUDART_INF_F;
    #pragma unroll
    for (int rr2 = 0; rr2 < RT; ++rr2)
        cmin = fminf(cmin,
            g_colpart[((b * RT + rr2) * CT + ctile) * CPB + ccx]);

    float s = rmin + cmin;
    int t = threadIdx.x;
    #pragma unroll
    for (int off = 16; off > 0; off >>= 1)
        s += __shfl_down_sync(0xffffffffu, s, off);
    if ((t & 31) == 0) wsum[t >> 5] = s;
    __syncthreads();
    if (t == 0) {
        float p = 0.0f;
        #pragma unroll
        for (int ww = 0; ww < RED_THREADS / 32; ++ww) p += wsum[ww];
        g_sum[blockIdx.x] = p;
        __threadfence();
        unsigned int v = atomicAdd(&g_ticket, 1u);
        s_last = (v == RED_BLOCKS - 1);
    }
    __syncthreads();

    // Deterministic final: exactly one block (the last to finish) reduces the
    // fixed-order g_sum array. Arithmetic order is independent of which block.
    if (s_last) {
        __threadfence();
        float fs = (t < RED_BLOCKS) ? g_sum[t] : 0.0f;
        #pragma unroll
        for (int off = 16; off > 0; off >>= 1)
            fs += __shfl_down_sync(0xffffffffu, fs, off);
        if ((t & 31) == 0) wsum[t >> 5] = fs;
        __syncthreads();
        if (t == 0) {
            float tot = 0.0f;
            #pragma unroll
            for (int ww = 0; ww < RED_BLOCKS / 32; ++ww) tot += wsum[ww];
            out[0] = tot * (1.0f / (float)(BATCH * NPTS));
            g_ticket = 0;   // reset for next graph replay
        }
    }
}

extern "C" void kernel_launch(void* const* d_in, const int* in_sizes, int n_in,
                              void* d_out, int out_size) {
    const float* p1 = (const float*)d_in[0];
    const float* p2 = (const float*)d_in[1];
    float* out = (float*)d_out;

    chamfer_main<<<MAIN_BLOCKS, THREADS>>>(p1, p2);
    chamfer_reduce<<<RED_BLOCKS, RED_THREADS>>>(out);
}